// round 1
// baseline (speedup 1.0000x reference)
#include <cuda_runtime.h>
#include <cuda_bf16.h>
#include <mma.h>

using namespace nvcuda;
typedef __nv_bfloat16 bf16;

#define Bsz 8192
#define Tn  12
#define DIN 64
#define HID 512
#define ENCD 128
#define Rr  64

// ---------------- device-global scratch (no runtime allocation allowed) ----------------
__device__ __align__(256) float g_enc[Bsz * Tn * ENCD];          // 50.3 MB fp32 encodings
__device__ __align__(256) float g_v[2][Bsz * Rr];                // ping-pong chain state
__device__ __align__(256) bf16  g_W1hi[HID * DIN],  g_W1lo[HID * DIN];
__device__ __align__(256) bf16  g_W2hi[ENCD * HID], g_W2lo[ENCD * HID];
__device__ __align__(256) bf16  g_Hmhi[(Tn - 2) * Rr * ENCD * Rr];
__device__ __align__(256) bf16  g_Hmlo[(Tn - 2) * Rr * ENCD * Rr];

// ---------------- prep: split fp32 weights into bf16 hi/lo pairs ----------------
__global__ void prep_kernel(const float* __restrict__ W1,
                            const float* __restrict__ W2,
                            const float* __restrict__ Hm) {
    const int n1 = HID * DIN;
    const int n2 = ENCD * HID;
    const int n3 = (Tn - 2) * Rr * ENCD * Rr;
    const int total = n1 + n2 + n3;
    for (int i = blockIdx.x * blockDim.x + threadIdx.x; i < total;
         i += gridDim.x * blockDim.x) {
        const float* s; bf16 *h, *l; int j;
        if (i < n1)            { s = W1; h = g_W1hi; l = g_W1lo; j = i; }
        else if (i < n1 + n2)  { s = W2; h = g_W2hi; l = g_W2lo; j = i - n1; }
        else                   { s = Hm; h = g_Hmhi; l = g_Hmlo; j = i - n1 - n2; }
        float v = s[j];
        bf16 hi = __float2bfloat16(v);
        h[j] = hi;
        l[j] = __float2bfloat16(v - __bfloat162float(hi));
    }
}

// ---------------- encoder: enc = relu(relu(x@W1^T+b1)@W2^T+b2), fused ----------------
// 32 rows per block, 128 threads (4 warps), bf16x3 wmma
#define ENC_SMEM (16384 + 2 * 32 * 520 * 2 + 2 * 32 * 72 * 2)   // 92160 B

__global__ __launch_bounds__(128) void encoder_kernel(const float* __restrict__ x,
                                                      const float* __restrict__ b1,
                                                      const float* __restrict__ b2) {
    extern __shared__ char smem[];
    float* staging = (float*)smem;                      // 4 warps * 16*64 fp32
    bf16* hs_hi = (bf16*)(smem + 16384);                // 32 x 520
    bf16* hs_lo = hs_hi + 32 * 520;
    bf16* xs_hi = hs_lo + 32 * 520;                     // 32 x 72
    bf16* xs_lo = xs_hi + 32 * 72;

    const int tid = threadIdx.x, w = tid >> 5, lane = tid & 31;
    const int n0 = blockIdx.x * 32;

    // load + split x tile [32 x 64]
    for (int idx = tid; idx < 32 * 64; idx += 128) {
        int r = idx >> 6, c = idx & 63;
        float v = x[(n0 + r) * DIN + c];
        bf16 hi = __float2bfloat16(v);
        xs_hi[r * 72 + c] = hi;
        xs_lo[r * 72 + c] = __float2bfloat16(v - __bfloat162float(hi));
    }
    __syncthreads();

    const int rw = w & 1, ch = w >> 1;
    float* stg = staging + w * 1024;

    // ---- stage 1: h[32,512] = relu(x @ W1^T + b1) ----
    for (int pass = 0; pass < 4; pass++) {
        const int cb = ch * 256 + pass * 64;
        wmma::fragment<wmma::accumulator, 16, 16, 16, float> acc[4];
        for (int ct = 0; ct < 4; ct++) wmma::fill_fragment(acc[ct], 0.0f);
        for (int kk = 0; kk < 4; kk++) {
            wmma::fragment<wmma::matrix_a, 16, 16, 16, bf16, wmma::row_major> ahi, alo;
            wmma::load_matrix_sync(ahi, xs_hi + rw * 16 * 72 + kk * 16, 72);
            wmma::load_matrix_sync(alo, xs_lo + rw * 16 * 72 + kk * 16, 72);
            for (int ct = 0; ct < 4; ct++) {
                wmma::fragment<wmma::matrix_b, 16, 16, 16, bf16, wmma::col_major> bhi, blo;
                wmma::load_matrix_sync(bhi, g_W1hi + (cb + ct * 16) * DIN + kk * 16, DIN);
                wmma::load_matrix_sync(blo, g_W1lo + (cb + ct * 16) * DIN + kk * 16, DIN);
                wmma::mma_sync(acc[ct], ahi, bhi, acc[ct]);
                wmma::mma_sync(acc[ct], alo, bhi, acc[ct]);
                wmma::mma_sync(acc[ct], ahi, blo, acc[ct]);
            }
        }
        for (int ct = 0; ct < 4; ct++)
            wmma::store_matrix_sync(stg + ct * 16, acc[ct], 64, wmma::mem_row_major);
        __syncwarp();
        for (int j = 0; j < 32; j++) {
            int idx = lane + j * 32;
            int r = idx >> 6, c = idx & 63;
            int gc = cb + c;
            float v = fmaxf(stg[idx] + b1[gc], 0.0f);
            bf16 hi = __float2bfloat16(v);
            hs_hi[(rw * 16 + r) * 520 + gc] = hi;
            hs_lo[(rw * 16 + r) * 520 + gc] = __float2bfloat16(v - __bfloat162float(hi));
        }
        __syncwarp();
    }
    __syncthreads();

    // ---- stage 2: enc[32,128] = relu(h @ W2^T + b2) ----
    {
        const int eh = ch;
        wmma::fragment<wmma::accumulator, 16, 16, 16, float> acc[4];
        for (int ct = 0; ct < 4; ct++) wmma::fill_fragment(acc[ct], 0.0f);
        for (int kk = 0; kk < 32; kk++) {
            wmma::fragment<wmma::matrix_a, 16, 16, 16, bf16, wmma::row_major> ahi, alo;
            wmma::load_matrix_sync(ahi, hs_hi + rw * 16 * 520 + kk * 16, 520);
            wmma::load_matrix_sync(alo, hs_lo + rw * 16 * 520 + kk * 16, 520);
            for (int ct = 0; ct < 4; ct++) {
                wmma::fragment<wmma::matrix_b, 16, 16, 16, bf16, wmma::col_major> bhi, blo;
                wmma::load_matrix_sync(bhi, g_W2hi + (eh * 64 + ct * 16) * HID + kk * 16, HID);
                wmma::load_matrix_sync(blo, g_W2lo + (eh * 64 + ct * 16) * HID + kk * 16, HID);
                wmma::mma_sync(acc[ct], ahi, bhi, acc[ct]);
                wmma::mma_sync(acc[ct], alo, bhi, acc[ct]);
                wmma::mma_sync(acc[ct], ahi, blo, acc[ct]);
            }
        }
        for (int ct = 0; ct < 4; ct++)
            wmma::store_matrix_sync(stg + ct * 16, acc[ct], 64, wmma::mem_row_major);
        __syncwarp();
        for (int j = 0; j < 32; j++) {
            int idx = lane + j * 32;
            int r = idx >> 6, c = idx & 63;
            int e = eh * 64 + c;
            g_enc[(n0 + rw * 16 + r) * ENCD + e] = fmaxf(stg[idx] + b2[e], 0.0f);
        }
    }
}

// ---------------- v0 = enc[:,0] @ H_first  (fp32 SIMT, exact) ----------------
__global__ __launch_bounds__(256) void v0_kernel(const float* __restrict__ Hf) {
    __shared__ float hf_s[ENCD * Rr];      // [e*64+r]
    __shared__ float enc_s[16][ENCD];
    const int tid = threadIdx.x;
    const int b0 = blockIdx.x * 16;
    for (int i = tid; i < ENCD * Rr; i += 256) hf_s[i] = Hf[i];
    for (int i = tid; i < 16 * ENCD; i += 256) {
        int j = i >> 7, e = i & 127;
        enc_s[j][e] = g_enc[(b0 + j) * Tn * ENCD + e];
    }
    __syncthreads();
    const int r = tid & 63, g = tid >> 6;
    for (int pass = 0; pass < 4; pass++) {
        int j = g * 4 + pass;
        float acc = 0.0f;
        for (int e = 0; e < ENCD; e++) acc += enc_s[j][e] * hf_s[e * 64 + r];
        g_v[0][(b0 + j) * 64 + r] = acc;
    }
}

// ---------------- chain step: v_new = (v outer enc) @ H_mid[t], bf16x3 wmma ----------------
#define CHAIN_SMEM (64 * 128 * 4 + 64 * 64 * 4 + 2 * 64 * 136 * 2)   // 83968 B

__global__ __launch_bounds__(256) void chain_kernel(int t) {
    extern __shared__ char smem[];
    float* enc_s = (float*)smem;                  // 64 x 128
    float* v_s   = enc_s + 64 * 128;              // 64 x 64
    bf16*  q_hi  = (bf16*)(v_s + 64 * 64);        // 64 x 136 (padded)
    bf16*  q_lo  = q_hi + 64 * 136;

    const float* vin  = g_v[t & 1];
    float*       vout = g_v[(t & 1) ^ 1];
    const bf16*  Hhi  = g_Hmhi + t * (Rr * ENCD * Rr);
    const bf16*  Hlo  = g_Hmlo + t * (Rr * ENCD * Rr);

    const int tid = threadIdx.x, w = tid >> 5;
    const int b0 = blockIdx.x * 64;
    const int tc = t + 1;

    for (int i = tid; i < 64 * 128; i += 256) {
        int r = i >> 7, e = i & 127;
        enc_s[i] = g_enc[((b0 + r) * Tn + tc) * ENCD + e];
    }
    for (int i = tid; i < 64 * 64; i += 256) v_s[i] = vin[b0 * 64 + i];

    wmma::fragment<wmma::accumulator, 16, 16, 16, float> acc[2];
    wmma::fill_fragment(acc[0], 0.0f);
    wmma::fill_fragment(acc[1], 0.0f);
    const int rt = w >> 1, cp = (w & 1) * 2;   // row tile 0..3, col tiles cp,cp+1
    __syncthreads();

    for (int p = 0; p < 64; p++) {
        // build Q slice: Q[i,e] = v[i,p] * enc[i,e], split to bf16 hi/lo
        #pragma unroll 4
        for (int k = 0; k < 32; k++) {
            int idx = tid + k * 256;
            int i = idx >> 7, e = idx & 127;
            float q = v_s[i * 64 + p] * enc_s[idx];
            bf16 hi = __float2bfloat16(q);
            q_hi[i * 136 + e] = hi;
            q_lo[i * 136 + e] = __float2bfloat16(q - __bfloat162float(hi));
        }
        __syncthreads();

        const bf16* Hp_hi = Hhi + p * (ENCD * Rr);
        const bf16* Hp_lo = Hlo + p * (ENCD * Rr);
        #pragma unroll
        for (int kk = 0; kk < 8; kk++) {
            wmma::fragment<wmma::matrix_a, 16, 16, 16, bf16, wmma::row_major> ahi, alo;
            wmma::load_matrix_sync(ahi, q_hi + rt * 16 * 136 + kk * 16, 136);
            wmma::load_matrix_sync(alo, q_lo + rt * 16 * 136 + kk * 16, 136);
            #pragma unroll
            for (int c = 0; c < 2; c++) {
                wmma::fragment<wmma::matrix_b, 16, 16, 16, bf16, wmma::row_major> bhi, blo;
                wmma::load_matrix_sync(bhi, Hp_hi + kk * 16 * 64 + (cp + c) * 16, 64);
                wmma::load_matrix_sync(blo, Hp_lo + kk * 16 * 64 + (cp + c) * 16, 64);
                wmma::mma_sync(acc[c], ahi, bhi, acc[c]);
                wmma::mma_sync(acc[c], alo, bhi, acc[c]);
                wmma::mma_sync(acc[c], ahi, blo, acc[c]);
            }
        }
        __syncthreads();
    }
    for (int c = 0; c < 2; c++)
        wmma::store_matrix_sync(vout + (b0 + rt * 16) * 64 + (cp + c) * 16,
                                acc[c], 64, wmma::mem_row_major);
}

// ---------------- final: out[b] = v . (H_last @ enc[:,T-1])  (fp32 SIMT) ----------------
__global__ __launch_bounds__(256) void final_kernel(const float* __restrict__ Hl,
                                                    float* __restrict__ out) {
    __shared__ float hl_t[ENCD * Rr];      // transposed: [e*64+p]
    __shared__ float enc_s[16][ENCD];
    __shared__ float red2[16][2];
    const int tid = threadIdx.x;
    const int b0 = blockIdx.x * 16;
    for (int i = tid; i < ENCD * Rr; i += 256) {
        int e = i >> 6, p = i & 63;
        hl_t[i] = Hl[p * ENCD + e];
    }
    for (int i = tid; i < 16 * ENCD; i += 256) {
        int j = i >> 7, e = i & 127;
        enc_s[j][e] = g_enc[((b0 + j) * Tn + (Tn - 1)) * ENCD + e];
    }
    __syncthreads();
    const int p = tid & 63, g = tid >> 6;          // g = 0..3
    const int warp = tid >> 5, half = warp & 1;
    for (int pass = 0; pass < 4; pass++) {
        int j = g * 4 + pass;
        float last = 0.0f;
        for (int e = 0; e < ENCD; e++) last += enc_s[j][e] * hl_t[e * 64 + p];
        float partial = g_v[0][(b0 + j) * 64 + p] * last;
        for (int off = 16; off > 0; off >>= 1)
            partial += __shfl_down_sync(0xffffffffu, partial, off);
        if ((tid & 31) == 0) red2[j][half] = partial;
    }
    __syncthreads();
    if (tid < 16) out[b0 + tid] = red2[tid][0] + red2[tid][1];
}

// ---------------- host launcher ----------------
extern "C" void kernel_launch(void* const* d_in, const int* in_sizes, int n_in,
                              void* d_out, int out_size) {
    const float* x  = (const float*)d_in[0];
    const float* W1 = (const float*)d_in[1];
    const float* b1 = (const float*)d_in[2];
    const float* W2 = (const float*)d_in[3];
    const float* b2 = (const float*)d_in[4];
    const float* Hf = (const float*)d_in[5];
    const float* Hm = (const float*)d_in[6];
    const float* Hl = (const float*)d_in[7];
    float* out = (float*)d_out;

    cudaFuncSetAttribute(encoder_kernel, cudaFuncAttributeMaxDynamicSharedMemorySize, ENC_SMEM);
    cudaFuncSetAttribute(chain_kernel,   cudaFuncAttributeMaxDynamicSharedMemorySize, CHAIN_SMEM);

    prep_kernel<<<4096, 256>>>(W1, W2, Hm);
    encoder_kernel<<<(Bsz * Tn) / 32, 128, ENC_SMEM>>>(x, b1, b2);
    v0_kernel<<<Bsz / 16, 256>>>(Hf);
    for (int t = 0; t < Tn - 2; t++)
        chain_kernel<<<Bsz / 64, 256, CHAIN_SMEM>>>(t);
    final_kernel<<<Bsz / 16, 256>>>(Hl, out);
}

// round 2
// speedup vs baseline: 2.5340x; 2.5340x over previous
#include <cuda_runtime.h>
#include <cuda_bf16.h>
#include <mma.h>

using namespace nvcuda;
typedef __nv_bfloat16 bf16;

#define Bsz 8192
#define Tn  12
#define DIN 64
#define HID 512
#define ENCD 128
#define Rr  64

// ---------------- device-global scratch ----------------
__device__ __align__(256) bf16  g_ench[Tn * Bsz * ENCD];   // enc hi, layout [t][b][e]
__device__ __align__(256) bf16  g_encl[Tn * Bsz * ENCD];   // enc lo
__device__ __align__(256) float g_v[2][Bsz * Rr];          // ping-pong chain state
__device__ __align__(256) bf16  g_W1hi[HID * DIN],  g_W1lo[HID * DIN];
__device__ __align__(256) bf16  g_W2hi[ENCD * HID], g_W2lo[ENCD * HID];
// H_mid transposed to GEMM-B layout: [t][e][r*64+p], hi/lo
__device__ __align__(256) bf16  g_HBh[(Tn - 2) * ENCD * Rr * Rr];
__device__ __align__(256) bf16  g_HBl[(Tn - 2) * ENCD * Rr * Rr];

// ---------------- prep: split W1/W2 into bf16 hi/lo ----------------
__global__ void prep_w_kernel(const float* __restrict__ W1,
                              const float* __restrict__ W2) {
    const int n1 = HID * DIN, n2 = ENCD * HID;
    for (int i = blockIdx.x * blockDim.x + threadIdx.x; i < n1 + n2;
         i += gridDim.x * blockDim.x) {
        const float* s; bf16 *h, *l; int j;
        if (i < n1) { s = W1; h = g_W1hi; l = g_W1lo; j = i; }
        else        { s = W2; h = g_W2hi; l = g_W2lo; j = i - n1; }
        float v = s[j];
        bf16 hi = __float2bfloat16(v);
        h[j] = hi;
        l[j] = __float2bfloat16(v - __bfloat162float(hi));
    }
}

// ---------------- prep: transpose H_mid[t,p,e,r] -> HB[t][e][r*64+p], split hi/lo ----------------
__global__ __launch_bounds__(256) void prep_hb_kernel(const float* __restrict__ Hm) {
    __shared__ float tile[64][65];              // [p][r]
    const int t = blockIdx.x >> 7;              // 0..9
    const int e = blockIdx.x & 127;             // 0..127
    const int tid = threadIdx.x;
    for (int i = tid; i < 64 * 64; i += 256) {
        int p = i >> 6, r = i & 63;
        tile[p][r] = Hm[(((t * 64 + p) * 128) + e) * 64 + r];
    }
    __syncthreads();
    bf16* dh = g_HBh + (t * 128 + e) * 4096;
    bf16* dl = g_HBl + (t * 128 + e) * 4096;
    for (int c = tid; c < 4096; c += 256) {
        int r = c >> 6, p = c & 63;
        float v = tile[p][r];
        bf16 hi = __float2bfloat16(v);
        dh[c] = hi;
        dl[c] = __float2bfloat16(v - __bfloat162float(hi));
    }
}

// ---------------- encoder: enc = relu(relu(x@W1^T+b1)@W2^T+b2), bf16x3 wmma ----------------
#define ENC_SMEM (16384 + 2 * 32 * 520 * 2 + 2 * 32 * 72 * 2)

__global__ __launch_bounds__(128) void encoder_kernel(const float* __restrict__ x,
                                                      const float* __restrict__ b1,
                                                      const float* __restrict__ b2) {
    extern __shared__ char smem[];
    float* staging = (float*)smem;
    bf16* hs_hi = (bf16*)(smem + 16384);
    bf16* hs_lo = hs_hi + 32 * 520;
    bf16* xs_hi = hs_lo + 32 * 520;
    bf16* xs_lo = xs_hi + 32 * 72;

    const int tid = threadIdx.x, w = tid >> 5, lane = tid & 31;
    const int n0 = blockIdx.x * 32;

    for (int idx = tid; idx < 32 * 64; idx += 128) {
        int r = idx >> 6, c = idx & 63;
        float v = x[(n0 + r) * DIN + c];
        bf16 hi = __float2bfloat16(v);
        xs_hi[r * 72 + c] = hi;
        xs_lo[r * 72 + c] = __float2bfloat16(v - __bfloat162float(hi));
    }
    __syncthreads();

    const int rw = w & 1, ch = w >> 1;
    float* stg = staging + w * 1024;

    for (int pass = 0; pass < 4; pass++) {
        const int cb = ch * 256 + pass * 64;
        wmma::fragment<wmma::accumulator, 16, 16, 16, float> acc[4];
        for (int ct = 0; ct < 4; ct++) wmma::fill_fragment(acc[ct], 0.0f);
        for (int kk = 0; kk < 4; kk++) {
            wmma::fragment<wmma::matrix_a, 16, 16, 16, bf16, wmma::row_major> ahi, alo;
            wmma::load_matrix_sync(ahi, xs_hi + rw * 16 * 72 + kk * 16, 72);
            wmma::load_matrix_sync(alo, xs_lo + rw * 16 * 72 + kk * 16, 72);
            for (int ct = 0; ct < 4; ct++) {
                wmma::fragment<wmma::matrix_b, 16, 16, 16, bf16, wmma::col_major> bhi, blo;
                wmma::load_matrix_sync(bhi, g_W1hi + (cb + ct * 16) * DIN + kk * 16, DIN);
                wmma::load_matrix_sync(blo, g_W1lo + (cb + ct * 16) * DIN + kk * 16, DIN);
                wmma::mma_sync(acc[ct], ahi, bhi, acc[ct]);
                wmma::mma_sync(acc[ct], alo, bhi, acc[ct]);
                wmma::mma_sync(acc[ct], ahi, blo, acc[ct]);
            }
        }
        for (int ct = 0; ct < 4; ct++)
            wmma::store_matrix_sync(stg + ct * 16, acc[ct], 64, wmma::mem_row_major);
        __syncwarp();
        for (int j = 0; j < 32; j++) {
            int idx = lane + j * 32;
            int r = idx >> 6, c = idx & 63;
            int gc = cb + c;
            float v = fmaxf(stg[idx] + b1[gc], 0.0f);
            bf16 hi = __float2bfloat16(v);
            hs_hi[(rw * 16 + r) * 520 + gc] = hi;
            hs_lo[(rw * 16 + r) * 520 + gc] = __float2bfloat16(v - __bfloat162float(hi));
        }
        __syncwarp();
    }
    __syncthreads();

    {
        const int eh = ch;
        wmma::fragment<wmma::accumulator, 16, 16, 16, float> acc[4];
        for (int ct = 0; ct < 4; ct++) wmma::fill_fragment(acc[ct], 0.0f);
        for (int kk = 0; kk < 32; kk++) {
            wmma::fragment<wmma::matrix_a, 16, 16, 16, bf16, wmma::row_major> ahi, alo;
            wmma::load_matrix_sync(ahi, hs_hi + rw * 16 * 520 + kk * 16, 520);
            wmma::load_matrix_sync(alo, hs_lo + rw * 16 * 520 + kk * 16, 520);
            for (int ct = 0; ct < 4; ct++) {
                wmma::fragment<wmma::matrix_b, 16, 16, 16, bf16, wmma::col_major> bhi, blo;
                wmma::load_matrix_sync(bhi, g_W2hi + (eh * 64 + ct * 16) * HID + kk * 16, HID);
                wmma::load_matrix_sync(blo, g_W2lo + (eh * 64 + ct * 16) * HID + kk * 16, HID);
                wmma::mma_sync(acc[ct], ahi, bhi, acc[ct]);
                wmma::mma_sync(acc[ct], alo, bhi, acc[ct]);
                wmma::mma_sync(acc[ct], ahi, blo, acc[ct]);
            }
        }
        for (int ct = 0; ct < 4; ct++)
            wmma::store_matrix_sync(stg + ct * 16, acc[ct], 64, wmma::mem_row_major);
        __syncwarp();
        for (int j = 0; j < 32; j++) {
            int idx = lane + j * 32;
            int r = idx >> 6, c = idx & 63;
            int e = eh * 64 + c;
            int n = n0 + rw * 16 + r;
            int b = n / Tn, tt = n % Tn;
            float v = fmaxf(stg[idx] + b2[e], 0.0f);
            bf16 hi = __float2bfloat16(v);
            g_ench[(tt * Bsz + b) * ENCD + e] = hi;
            g_encl[(tt * Bsz + b) * ENCD + e] = __float2bfloat16(v - __bfloat162float(hi));
        }
    }
}

// ---------------- v0 = enc[:,0] @ H_first (fp32 SIMT) ----------------
__global__ __launch_bounds__(256) void v0_kernel(const float* __restrict__ Hf) {
    __shared__ float hf_s[ENCD * Rr];
    __shared__ float enc_s[16][ENCD];
    const int tid = threadIdx.x;
    const int b0 = blockIdx.x * 16;
    for (int i = tid; i < ENCD * Rr; i += 256) hf_s[i] = Hf[i];
    for (int i = tid; i < 16 * ENCD; i += 256) {
        int j = i >> 7, e = i & 127;
        int a = (b0 + j) * ENCD + e;           // t=0 plane
        enc_s[j][e] = __bfloat162float(g_ench[a]) + __bfloat162float(g_encl[a]);
    }
    __syncthreads();
    const int r = tid & 63, g = tid >> 6;
    for (int pass = 0; pass < 4; pass++) {
        int j = g * 4 + pass;
        float acc = 0.0f;
        for (int e = 0; e < ENCD; e++) acc += enc_s[j][e] * hf_s[e * 64 + r];
        g_v[0][(b0 + j) * 64 + r] = acc;
    }
}

// ---------------- chain step t: GEMM [64b x 512col] tile, K=128, fused p-reduction ----------------
// col = r*64 + p  ->  block owns 8 r values, ALL p  ->  warp-local reduction, direct store.
#define CHM_SMEM (16384 + 2*64*72*2 + 2*64*528*2 + 8*16*20*4)   // 180224 B

__global__ __launch_bounds__(256, 1) void chainM_kernel(int t) {
    extern __shared__ char smem[];
    float* v_s  = (float*)smem;                      // 64 x 64
    bf16*  As_h = (bf16*)(smem + 16384);             // 64 x 72
    bf16*  As_l = As_h + 64 * 72;
    bf16*  Bs_h = As_l + 64 * 72;                    // 64 x 528
    bf16*  Bs_l = Bs_h + 64 * 528;
    float* stg_base = (float*)(Bs_l + 64 * 528);     // 8 warps x 16x20

    const float* vin  = g_v[t & 1];
    float*       vout = g_v[(t & 1) ^ 1];
    const bf16*  HBh  = g_HBh + t * (ENCD * 4096);
    const bf16*  HBl  = g_HBl + t * (ENCD * 4096);
    const bf16*  Eh   = g_ench + (t + 1) * (Bsz * ENCD);
    const bf16*  El   = g_encl + (t + 1) * (Bsz * ENCD);

    const int tid = threadIdx.x, w = tid >> 5, lane = tid & 31;
    const int cb = blockIdx.x * 512;                 // col base (8 r's)
    const int b0 = blockIdx.y * 64;                  // batch base
    const int rg = w >> 2, cg = w & 3;               // warp 2x4 grid
    float* stg = stg_base + w * (16 * 20);

    for (int i = tid; i < 64 * 64; i += 256) v_s[i] = vin[b0 * 64 + i];

    wmma::fragment<wmma::accumulator, 16, 16, 16, float> acc[2][8];
    #pragma unroll
    for (int rf = 0; rf < 2; rf++)
        #pragma unroll
        for (int j = 0; j < 8; j++) wmma::fill_fragment(acc[rf][j], 0.0f);

    for (int chunk = 0; chunk < 2; chunk++) {
        const int k0 = chunk * 64;
        __syncthreads();
        // load A (enc) chunk: 64 rows x 64 e, vectorized 8 bf16
        for (int i = tid; i < 512; i += 256) {
            int r = i >> 3, c8 = (i & 7) * 8;
            const uint4* sh = (const uint4*)(Eh + (size_t)(b0 + r) * ENCD + k0 + c8);
            const uint4* sl = (const uint4*)(El + (size_t)(b0 + r) * ENCD + k0 + c8);
            *(uint4*)(As_h + r * 72 + c8) = *sh;
            *(uint4*)(As_l + r * 72 + c8) = *sl;
        }
        // load B (H) chunk: 64 e-rows x 512 cols
        for (int i = tid; i < 4096; i += 256) {
            int e = i >> 6, c8 = (i & 63) * 8;
            const uint4* sh = (const uint4*)(HBh + (size_t)(k0 + e) * 4096 + cb + c8);
            const uint4* sl = (const uint4*)(HBl + (size_t)(k0 + e) * 4096 + cb + c8);
            *(uint4*)(Bs_h + e * 528 + c8) = *sh;
            *(uint4*)(Bs_l + e * 528 + c8) = *sl;
        }
        __syncthreads();

        #pragma unroll
        for (int kk = 0; kk < 4; kk++) {
            wmma::fragment<wmma::matrix_a, 16, 16, 16, bf16, wmma::row_major> ahi[2], alo[2];
            #pragma unroll
            for (int rf = 0; rf < 2; rf++) {
                wmma::load_matrix_sync(ahi[rf], As_h + (rg * 32 + rf * 16) * 72 + kk * 16, 72);
                wmma::load_matrix_sync(alo[rf], As_l + (rg * 32 + rf * 16) * 72 + kk * 16, 72);
            }
            #pragma unroll
            for (int j = 0; j < 8; j++) {
                wmma::fragment<wmma::matrix_b, 16, 16, 16, bf16, wmma::row_major> bhi, blo;
                wmma::load_matrix_sync(bhi, Bs_h + (kk * 16) * 528 + cg * 128 + j * 16, 528);
                wmma::load_matrix_sync(blo, Bs_l + (kk * 16) * 528 + cg * 128 + j * 16, 528);
                #pragma unroll
                for (int rf = 0; rf < 2; rf++) {
                    wmma::mma_sync(acc[rf][j], ahi[rf], bhi, acc[rf][j]);
                    wmma::mma_sync(acc[rf][j], alo[rf], bhi, acc[rf][j]);
                    wmma::mma_sync(acc[rf][j], ahi[rf], blo, acc[rf][j]);
                }
            }
        }
    }

    // ---- fused epilogue: v_new[b,r] = sum_p M[b,(r,p)] * v[b,p], warp-local ----
    float racc[2][2] = {{0.f, 0.f}, {0.f, 0.f}};
    const int row16 = lane >> 1, half = lane & 1;
    #pragma unroll
    for (int rf = 0; rf < 2; rf++) {
        #pragma unroll
        for (int j = 0; j < 8; j++) {
            wmma::store_matrix_sync(stg, acc[rf][j], 20, wmma::mem_row_major);
            __syncwarp();
            const int p0 = 16 * (j & 3) + half * 8;
            const int bl = rg * 32 + rf * 16 + row16;
            float s = 0.f;
            #pragma unroll
            for (int c = 0; c < 8; c++)
                s += stg[row16 * 20 + half * 8 + c] * v_s[bl * 64 + p0 + c];
            s += __shfl_xor_sync(0xffffffffu, s, 1);
            racc[rf][j >> 2] += s;
            __syncwarp();
        }
    }
    if (half == 0) {
        #pragma unroll
        for (int rf = 0; rf < 2; rf++)
            #pragma unroll
            for (int rr = 0; rr < 2; rr++) {
                int b = b0 + rg * 32 + rf * 16 + row16;
                int r = (cb >> 6) + 2 * cg + rr;
                vout[b * 64 + r] = racc[rf][rr];
            }
    }
}

// ---------------- final: out[b] = v . (H_last @ enc[:,T-1]) ----------------
__global__ __launch_bounds__(256) void final_kernel(const float* __restrict__ Hl,
                                                    float* __restrict__ out) {
    __shared__ float hl_t[ENCD * Rr];
    __shared__ float enc_s[16][ENCD];
    __shared__ float red2[16][2];
    const int tid = threadIdx.x;
    const int b0 = blockIdx.x * 16;
    for (int i = tid; i < ENCD * Rr; i += 256) {
        int e = i >> 6, p = i & 63;
        hl_t[i] = Hl[p * ENCD + e];
    }
    for (int i = tid; i < 16 * ENCD; i += 256) {
        int j = i >> 7, e = i & 127;
        int a = ((Tn - 1) * Bsz + b0 + j) * ENCD + e;
        enc_s[j][e] = __bfloat162float(g_ench[a]) + __bfloat162float(g_encl[a]);
    }
    __syncthreads();
    const int p = tid & 63, g = tid >> 6;
    const int warp = tid >> 5, half = warp & 1;
    for (int pass = 0; pass < 4; pass++) {
        int j = g * 4 + pass;
        float last = 0.0f;
        for (int e = 0; e < ENCD; e++) last += enc_s[j][e] * hl_t[e * 64 + p];
        float partial = g_v[0][(b0 + j) * 64 + p] * last;
        for (int off = 16; off > 0; off >>= 1)
            partial += __shfl_down_sync(0xffffffffu, partial, off);
        if ((tid & 31) == 0) red2[j][half] = partial;
    }
    __syncthreads();
    if (tid < 16) out[b0 + tid] = red2[tid][0] + red2[tid][1];
}

// ---------------- host launcher ----------------
extern "C" void kernel_launch(void* const* d_in, const int* in_sizes, int n_in,
                              void* d_out, int out_size) {
    const float* x  = (const float*)d_in[0];
    const float* W1 = (const float*)d_in[1];
    const float* b1 = (const float*)d_in[2];
    const float* W2 = (const float*)d_in[3];
    const float* b2 = (const float*)d_in[4];
    const float* Hf = (const float*)d_in[5];
    const float* Hm = (const float*)d_in[6];
    const float* Hl = (const float*)d_in[7];
    float* out = (float*)d_out;

    cudaFuncSetAttribute(encoder_kernel, cudaFuncAttributeMaxDynamicSharedMemorySize, ENC_SMEM);
    cudaFuncSetAttribute(chainM_kernel,  cudaFuncAttributeMaxDynamicSharedMemorySize, CHM_SMEM);

    prep_w_kernel<<<96, 256>>>(W1, W2);
    prep_hb_kernel<<<(Tn - 2) * ENCD, 256>>>(Hm);
    encoder_kernel<<<(Bsz * Tn) / 32, 128, ENC_SMEM>>>(x, b1, b2);
    v0_kernel<<<Bsz / 16, 256>>>(Hf);
    for (int t = 0; t < Tn - 2; t++)
        chainM_kernel<<<dim3(8, 128), 256, CHM_SMEM>>>(t);
    final_kernel<<<Bsz / 16, 256>>>(Hl, out);
}

// round 4
// speedup vs baseline: 3.1041x; 1.2250x over previous
#include <cuda_runtime.h>
#include <cuda_bf16.h>
#include <mma.h>
#include <cstdint>

using namespace nvcuda;
typedef __nv_bfloat16 bf16;

#define Bsz 8192
#define Tn  12
#define DIN 64
#define HID 512
#define ENCD 128
#define Rr  64

// ================= device-global scratch =================
__device__ __align__(256) bf16  g_ench[Tn * Bsz * ENCD];   // [t][b][e] hi
__device__ __align__(256) bf16  g_encl[Tn * Bsz * ENCD];   // lo
__device__ __align__(256) float g_v[2][Bsz * Rr];
__device__ __align__(256) bf16  g_W1hi[HID * DIN],  g_W1lo[HID * DIN];
__device__ __align__(256) bf16  g_W2hi[ENCD * HID], g_W2lo[ENCD * HID];
// H_mid as GEMM-B: [t][e][n = r*64+p]  (row-major over k=e, row stride 4096)
__device__ __align__(256) bf16  g_HBh[(Tn - 2) * ENCD * Rr * Rr];
__device__ __align__(256) bf16  g_HBl[(Tn - 2) * ENCD * Rr * Rr];

// cp.async helpers (sm_80 path — safe on compute_103)
__device__ __forceinline__ uint32_t smem_u32(const void* p) {
    uint32_t a;
    asm("{ .reg .u64 t; cvta.to.shared.u64 t, %1; cvt.u32.u64 %0, t; }" : "=r"(a) : "l"(p));
    return a;
}
__device__ __forceinline__ void cp16(uint32_t dst, const void* src) {
    asm volatile("cp.async.cg.shared.global [%0], [%1], 16;" :: "r"(dst), "l"(src));
}
#define CP_COMMIT()  asm volatile("cp.async.commit_group;")
#define CP_WAIT(N)   asm volatile("cp.async.wait_group %0;" :: "n"(N))

// ================= prep: W splits =================
__global__ void prep_w_kernel(const float* __restrict__ W1,
                              const float* __restrict__ W2) {
    const int n1 = HID * DIN, n2 = ENCD * HID;
    for (int i = blockIdx.x * blockDim.x + threadIdx.x; i < n1 + n2;
         i += gridDim.x * blockDim.x) {
        const float* s; bf16 *h, *l; int j;
        if (i < n1) { s = W1; h = g_W1hi; l = g_W1lo; j = i; }
        else        { s = W2; h = g_W2hi; l = g_W2lo; j = i - n1; }
        float v = s[j];
        bf16 hi = __float2bfloat16(v);
        h[j] = hi;
        l[j] = __float2bfloat16(v - __bfloat162float(hi));
    }
}

// ================= prep: Hm[t,p,e,r] -> HB[t][e][r*64+p] hi/lo =================
__global__ __launch_bounds__(256) void prep_hb_kernel(const float* __restrict__ Hm) {
    __shared__ float tile[64][65];              // [p][r]
    const int t = blockIdx.x >> 7;
    const int e = blockIdx.x & 127;
    const int tid = threadIdx.x;
    for (int i = tid; i < 64 * 64; i += 256) {
        int p = i >> 6, r = i & 63;
        tile[p][r] = Hm[(((size_t)(t * 64 + p) * 128) + e) * 64 + r];
    }
    __syncthreads();
    bf16* dh = g_HBh + (size_t)(t * 128 + e) * 4096;
    bf16* dl = g_HBl + (size_t)(t * 128 + e) * 4096;
    for (int c = tid; c < 4096; c += 256) {
        int r = c >> 6, p = c & 63;
        float v = tile[p][r];
        bf16 hi = __float2bfloat16(v);
        dh[c] = hi;
        dl[c] = __float2bfloat16(v - __bfloat162float(hi));
    }
}

// ================= encoder (wmma bf16x3, as in R2) =================
#define ENC_SMEM (16384 + 2 * 32 * 520 * 2 + 2 * 32 * 72 * 2)

__global__ __launch_bounds__(128) void encoder_kernel(const float* __restrict__ x,
                                                      const float* __restrict__ b1,
                                                      const float* __restrict__ b2) {
    extern __shared__ char smem[];
    float* staging = (float*)smem;
    bf16* hs_hi = (bf16*)(smem + 16384);
    bf16* hs_lo = hs_hi + 32 * 520;
    bf16* xs_hi = hs_lo + 32 * 520;
    bf16* xs_lo = xs_hi + 32 * 72;

    const int tid = threadIdx.x, w = tid >> 5, lane = tid & 31;
    const int n0 = blockIdx.x * 32;

    for (int idx = tid; idx < 32 * 64; idx += 128) {
        int r = idx >> 6, c = idx & 63;
        float v = x[(size_t)(n0 + r) * DIN + c];
        bf16 hi = __float2bfloat16(v);
        xs_hi[r * 72 + c] = hi;
        xs_lo[r * 72 + c] = __float2bfloat16(v - __bfloat162float(hi));
    }
    __syncthreads();

    const int rw = w & 1, ch = w >> 1;
    float* stg = staging + w * 1024;

    for (int pass = 0; pass < 4; pass++) {
        const int cb = ch * 256 + pass * 64;
        wmma::fragment<wmma::accumulator, 16, 16, 16, float> acc[4];
        for (int ct = 0; ct < 4; ct++) wmma::fill_fragment(acc[ct], 0.0f);
        for (int kk = 0; kk < 4; kk++) {
            wmma::fragment<wmma::matrix_a, 16, 16, 16, bf16, wmma::row_major> ahi, alo;
            wmma::load_matrix_sync(ahi, xs_hi + rw * 16 * 72 + kk * 16, 72);
            wmma::load_matrix_sync(alo, xs_lo + rw * 16 * 72 + kk * 16, 72);
            for (int ct = 0; ct < 4; ct++) {
                wmma::fragment<wmma::matrix_b, 16, 16, 16, bf16, wmma::col_major> bhi, blo;
                wmma::load_matrix_sync(bhi, g_W1hi + (cb + ct * 16) * DIN + kk * 16, DIN);
                wmma::load_matrix_sync(blo, g_W1lo + (cb + ct * 16) * DIN + kk * 16, DIN);
                wmma::mma_sync(acc[ct], ahi, bhi, acc[ct]);
                wmma::mma_sync(acc[ct], alo, bhi, acc[ct]);
                wmma::mma_sync(acc[ct], ahi, blo, acc[ct]);
            }
        }
        for (int ct = 0; ct < 4; ct++)
            wmma::store_matrix_sync(stg + ct * 16, acc[ct], 64, wmma::mem_row_major);
        __syncwarp();
        for (int j = 0; j < 32; j++) {
            int idx = lane + j * 32;
            int r = idx >> 6, c = idx & 63;
            int gc = cb + c;
            float v = fmaxf(stg[idx] + b1[gc], 0.0f);
            bf16 hi = __float2bfloat16(v);
            hs_hi[(rw * 16 + r) * 520 + gc] = hi;
            hs_lo[(rw * 16 + r) * 520 + gc] = __float2bfloat16(v - __bfloat162float(hi));
        }
        __syncwarp();
    }
    __syncthreads();

    {
        const int eh = ch;
        wmma::fragment<wmma::accumulator, 16, 16, 16, float> acc[4];
        for (int ct = 0; ct < 4; ct++) wmma::fill_fragment(acc[ct], 0.0f);
        for (int kk = 0; kk < 32; kk++) {
            wmma::fragment<wmma::matrix_a, 16, 16, 16, bf16, wmma::row_major> ahi, alo;
            wmma::load_matrix_sync(ahi, hs_hi + rw * 16 * 520 + kk * 16, 520);
            wmma::load_matrix_sync(alo, hs_lo + rw * 16 * 520 + kk * 16, 520);
            for (int ct = 0; ct < 4; ct++) {
                wmma::fragment<wmma::matrix_b, 16, 16, 16, bf16, wmma::col_major> bhi, blo;
                wmma::load_matrix_sync(bhi, g_W2hi + (eh * 64 + ct * 16) * HID + kk * 16, HID);
                wmma::load_matrix_sync(blo, g_W2lo + (eh * 64 + ct * 16) * HID + kk * 16, HID);
                wmma::mma_sync(acc[ct], ahi, bhi, acc[ct]);
                wmma::mma_sync(acc[ct], alo, bhi, acc[ct]);
                wmma::mma_sync(acc[ct], ahi, blo, acc[ct]);
            }
        }
        for (int ct = 0; ct < 4; ct++)
            wmma::store_matrix_sync(stg + ct * 16, acc[ct], 64, wmma::mem_row_major);
        __syncwarp();
        for (int j = 0; j < 32; j++) {
            int idx = lane + j * 32;
            int r = idx >> 6, c = idx & 63;
            int e = eh * 64 + c;
            int n = n0 + rw * 16 + r;
            int b = n / Tn, tt = n % Tn;
            float v = fmaxf(stg[idx] + b2[e], 0.0f);
            bf16 hi = __float2bfloat16(v);
            g_ench[(size_t)(tt * Bsz + b) * ENCD + e] = hi;
            g_encl[(size_t)(tt * Bsz + b) * ENCD + e] = __float2bfloat16(v - __bfloat162float(hi));
        }
    }
}

// ================= v0 = enc[:,0] @ H_first =================
__global__ __launch_bounds__(256) void v0_kernel(const float* __restrict__ Hf) {
    __shared__ float hf_s[ENCD * Rr];
    __shared__ float enc_s[16][ENCD];
    const int tid = threadIdx.x;
    const int b0 = blockIdx.x * 16;
    for (int i = tid; i < ENCD * Rr; i += 256) hf_s[i] = Hf[i];
    for (int i = tid; i < 16 * ENCD; i += 256) {
        int j = i >> 7, e = i & 127;
        size_t a = (size_t)(b0 + j) * ENCD + e;
        enc_s[j][e] = __bfloat162float(g_ench[a]) + __bfloat162float(g_encl[a]);
    }
    __syncthreads();
    const int r = tid & 63, g = tid >> 6;
    for (int pass = 0; pass < 4; pass++) {
        int j = g * 4 + pass;
        float acc = 0.0f;
        for (int e = 0; e < ENCD; e++) acc += enc_s[j][e] * hf_s[e * 64 + r];
        g_v[0][(b0 + j) * 64 + r] = acc;
    }
}

// ================= chain step: pipelined wmma bf16x3, fused p-reduction =================
// CTA 128b x 256 cols (4 r's), K=128 in 4 chunks of 32, cp.async 2-stage pipeline.
// 512 threads, warp grid 4x4; each warp's 64-col group = exactly one r, all p.
#define AP 40        // A smem row pad (bf16)
#define BP 264       // B smem row pad (bf16)
#define A_STG (128 * AP)             // bf16 per A buffer
#define B_STG (32 * BP)              // bf16 per B buffer
// layout (bytes): Ah[2 stg] Al[2] Bh[2] Bl[2] | v_s | stg
#define OFF_AH 0u
#define OFF_AL (OFF_AH + 2u * A_STG * 2u)
#define OFF_BH (OFF_AL + 2u * A_STG * 2u)
#define OFF_BL (OFF_BH + 2u * B_STG * 2u)
#define OFF_V  (OFF_BL + 2u * B_STG * 2u)
#define OFF_ST (OFF_V + 128u * 65u * 4u)
#define CH_SMEM (OFF_ST + 16u * 320u * 4u)      // 162304 B

__global__ __launch_bounds__(512, 1) void chain_pipe_kernel(int t) {
    extern __shared__ char smem[];
    bf16* Ah[2] = { (bf16*)(smem + OFF_AH), (bf16*)(smem + OFF_AH) + A_STG };
    bf16* Al[2] = { (bf16*)(smem + OFF_AL), (bf16*)(smem + OFF_AL) + A_STG };
    bf16* Bh[2] = { (bf16*)(smem + OFF_BH), (bf16*)(smem + OFF_BH) + B_STG };
    bf16* Bl[2] = { (bf16*)(smem + OFF_BL), (bf16*)(smem + OFF_BL) + B_STG };
    float* v_s = (float*)(smem + OFF_V);
    float* stg_base = (float*)(smem + OFF_ST);

    const int tid = threadIdx.x, wid = tid >> 5, lane = tid & 31;
    const int wy = wid >> 2, wx = wid & 3;
    const int cb = blockIdx.x * 256;           // col base (4 r's)
    const int b0 = blockIdx.y * 128;           // batch base

    const bf16* Eh  = g_ench + (size_t)(t + 1) * Bsz * ENCD;
    const bf16* El  = g_encl + (size_t)(t + 1) * Bsz * ENCD;
    const bf16* HBh = g_HBh + (size_t)t * ENCD * 4096;
    const bf16* HBl = g_HBl + (size_t)t * ENCD * 4096;
    const float* vin  = g_v[t & 1];
    float*       vout = g_v[(t & 1) ^ 1];

    // async-load one K-chunk (32 k) into stage s
    auto load_chunk = [&](int c, int s) {
        const int k0 = c * 32;
        {   // A hi/lo: 512 x 16B each -> 1 per thread
            int r = tid >> 2, kq = (tid & 3) * 8;
            uint32_t d = smem_u32(Ah[s] + r * AP + kq);
            cp16(d, Eh + (size_t)(b0 + r) * ENCD + k0 + kq);
            d = smem_u32(Al[s] + r * AP + kq);
            cp16(d, El + (size_t)(b0 + r) * ENCD + k0 + kq);
        }
        #pragma unroll
        for (int q = 0; q < 2; q++) {   // B hi/lo: 1024 x 16B each -> 2 per thread
            int idx = tid + q * 512;
            int e = idx >> 5, cq = (idx & 31) * 8;
            uint32_t d = smem_u32(Bh[s] + e * BP + cq);
            cp16(d, HBh + (size_t)(k0 + e) * 4096 + cb + cq);
            d = smem_u32(Bl[s] + e * BP + cq);
            cp16(d, HBl + (size_t)(k0 + e) * 4096 + cb + cq);
        }
        CP_COMMIT();
    };

    // v_s[128][65]
    #pragma unroll
    for (int q = 0; q < 16; q++) {
        int i = tid + q * 512;
        int m = i >> 6, p = i & 63;
        v_s[m * 65 + p] = vin[(size_t)(b0 + m) * 64 + p];
    }

    wmma::fragment<wmma::accumulator, 16, 16, 16, float> acc[2][4];
    #pragma unroll
    for (int rf = 0; rf < 2; rf++)
        #pragma unroll
        for (int j = 0; j < 4; j++) wmma::fill_fragment(acc[rf][j], 0.0f);

    load_chunk(0, 0);

    #pragma unroll
    for (int c = 0; c < 4; c++) {
        if (c < 3) { load_chunk(c + 1, (c + 1) & 1); CP_WAIT(1); }
        else       { CP_WAIT(0); }
        __syncthreads();
        const int s = c & 1;
        #pragma unroll
        for (int kk = 0; kk < 2; kk++) {
            wmma::fragment<wmma::matrix_a, 16, 16, 16, bf16, wmma::row_major> ahi[2], alo[2];
            #pragma unroll
            for (int rf = 0; rf < 2; rf++) {
                wmma::load_matrix_sync(ahi[rf], Ah[s] + (wy * 32 + rf * 16) * AP + kk * 16, AP);
                wmma::load_matrix_sync(alo[rf], Al[s] + (wy * 32 + rf * 16) * AP + kk * 16, AP);
            }
            #pragma unroll
            for (int j = 0; j < 4; j++) {
                wmma::fragment<wmma::matrix_b, 16, 16, 16, bf16, wmma::row_major> bhi, blo;
                wmma::load_matrix_sync(bhi, Bh[s] + (kk * 16) * BP + wx * 64 + j * 16, BP);
                wmma::load_matrix_sync(blo, Bl[s] + (kk * 16) * BP + wx * 64 + j * 16, BP);
                #pragma unroll
                for (int rf = 0; rf < 2; rf++) {
                    wmma::mma_sync(acc[rf][j], ahi[rf], bhi, acc[rf][j]);
                    wmma::mma_sync(acc[rf][j], alo[rf], bhi, acc[rf][j]);
                    wmma::mma_sync(acc[rf][j], ahi[rf], blo, acc[rf][j]);
                }
            }
        }
        __syncthreads();
    }

    // ---- epilogue: each warp owns r = blockIdx.x*4 + wx, rows wy*32..wy*32+31 ----
    float* stg = stg_base + wid * 320;
    const int row16 = lane >> 1, half = lane & 1;
    const int r_glob = blockIdx.x * 4 + wx;
    float racc[2] = {0.f, 0.f};
    #pragma unroll
    for (int rf = 0; rf < 2; rf++) {
        #pragma unroll
        for (int j = 0; j < 4; j++) {
            wmma::store_matrix_sync(stg, acc[rf][j], 20, wmma::mem_row_major);
            __syncwarp();
            const int p0 = j * 16 + half * 8;
            const int bl = wy * 32 + rf * 16 + row16;
            float ssum = 0.f;
            #pragma unroll
            for (int cc = 0; cc < 8; cc++)
                ssum += stg[row16 * 20 + half * 8 + cc] * v_s[bl * 65 + p0 + cc];
            ssum += __shfl_xor_sync(0xffffffffu, ssum, 1);
            racc[rf] += ssum;
            __syncwarp();
        }
    }
    if (half == 0) {
        #pragma unroll
        for (int rf = 0; rf < 2; rf++) {
            int b = b0 + wy * 32 + rf * 16 + row16;
            vout[(size_t)b * 64 + r_glob] = racc[rf];
        }
    }
}

// ================= final: out[b] = v . (H_last @ enc[:,T-1]) =================
__global__ __launch_bounds__(256) void final_kernel(const float* __restrict__ Hl,
                                                    float* __restrict__ out) {
    __shared__ float hl_t[ENCD * Rr];
    __shared__ float enc_s[16][ENCD];
    __shared__ float red2[16][2];
    const int tid = threadIdx.x;
    const int b0 = blockIdx.x * 16;
    for (int i = tid; i < ENCD * Rr; i += 256) {
        int e = i >> 6, p = i & 63;
        hl_t[i] = Hl[p * ENCD + e];
    }
    for (int i = tid; i < 16 * ENCD; i += 256) {
        int j = i >> 7, e = i & 127;
        size_t a = (size_t)((Tn - 1) * Bsz + b0 + j) * ENCD + e;
        enc_s[j][e] = __bfloat162float(g_ench[a]) + __bfloat162float(g_encl[a]);
    }
    __syncthreads();
    const int p = tid & 63, g = tid >> 6;
    const int warp = tid >> 5, half = warp & 1;
    for (int pass = 0; pass < 4; pass++) {
        int j = g * 4 + pass;
        float last = 0.0f;
        for (int e = 0; e < ENCD; e++) last += enc_s[j][e] * hl_t[e * 64 + p];
        float partial = g_v[0][(b0 + j) * 64 + p] * last;
        for (int off = 16; off > 0; off >>= 1)
            partial += __shfl_down_sync(0xffffffffu, partial, off);
        if ((tid & 31) == 0) red2[j][half] = partial;
    }
    __syncthreads();
    if (tid < 16) out[b0 + tid] = red2[tid][0] + red2[tid][1];
}

// ================= host launcher =================
extern "C" void kernel_launch(void* const* d_in, const int* in_sizes, int n_in,
                              void* d_out, int out_size) {
    const float* x  = (const float*)d_in[0];
    const float* W1 = (const float*)d_in[1];
    const float* b1 = (const float*)d_in[2];
    const float* W2 = (const float*)d_in[3];
    const float* b2 = (const float*)d_in[4];
    const float* Hf = (const float*)d_in[5];
    const float* Hm = (const float*)d_in[6];
    const float* Hl = (const float*)d_in[7];
    float* out = (float*)d_out;

    cudaFuncSetAttribute(encoder_kernel,    cudaFuncAttributeMaxDynamicSharedMemorySize, ENC_SMEM);
    cudaFuncSetAttribute(chain_pipe_kernel, cudaFuncAttributeMaxDynamicSharedMemorySize, CH_SMEM);

    prep_w_kernel<<<96, 256>>>(W1, W2);
    prep_hb_kernel<<<(Tn - 2) * ENCD, 256>>>(Hm);
    encoder_kernel<<<(Bsz * Tn) / 32, 128, ENC_SMEM>>>(x, b1, b2);
    v0_kernel<<<Bsz / 16, 256>>>(Hf);
    for (int t = 0; t < Tn - 2; t++)
        chain_pipe_kernel<<<dim3(16, 64), 512, CH_SMEM>>>(t);
    final_kernel<<<Bsz / 16, 256>>>(Hl, out);
}

// round 5
// speedup vs baseline: 3.3410x; 1.0763x over previous
#include <cuda_runtime.h>
#include <cuda_bf16.h>
#include <mma.h>
#include <cstdint>

using namespace nvcuda;
typedef __nv_bfloat16 bf16;

#define Bsz 8192
#define Tn  12
#define DIN 64
#define HID 512
#define ENCD 128
#define Rr  64

// ================= device-global scratch =================
__device__ __align__(256) bf16  g_ench[Tn * Bsz * ENCD];   // [t][b][e] hi
__device__ __align__(256) bf16  g_encl[Tn * Bsz * ENCD];   // lo
__device__ __align__(256) float g_v[2][Bsz * Rr];
__device__ __align__(256) bf16  g_W1hi[HID * DIN],  g_W1lo[HID * DIN];
__device__ __align__(256) bf16  g_W2hi[ENCD * HID], g_W2lo[ENCD * HID];
// H_mid as GEMM-B: [t][e][n = r*64+p]
__device__ __align__(256) bf16  g_HBh[(Tn - 2) * ENCD * Rr * Rr];
__device__ __align__(256) bf16  g_HBl[(Tn - 2) * ENCD * Rr * Rr];

__device__ __forceinline__ uint32_t smem_u32(const void* p) {
    uint32_t a;
    asm("{ .reg .u64 t; cvta.to.shared.u64 t, %1; cvt.u32.u64 %0, t; }" : "=r"(a) : "l"(p));
    return a;
}
__device__ __forceinline__ void cp16(uint32_t dst, const void* src) {
    asm volatile("cp.async.cg.shared.global [%0], [%1], 16;" :: "r"(dst), "l"(src));
}
#define CP_COMMIT()  asm volatile("cp.async.commit_group;")
#define CP_WAIT(N)   asm volatile("cp.async.wait_group %0;" :: "n"(N))

// ================= prep: W splits =================
__global__ void prep_w_kernel(const float* __restrict__ W1,
                              const float* __restrict__ W2) {
    const int n1 = HID * DIN, n2 = ENCD * HID;
    for (int i = blockIdx.x * blockDim.x + threadIdx.x; i < n1 + n2;
         i += gridDim.x * blockDim.x) {
        const float* s; bf16 *h, *l; int j;
        if (i < n1) { s = W1; h = g_W1hi; l = g_W1lo; j = i; }
        else        { s = W2; h = g_W2hi; l = g_W2lo; j = i - n1; }
        float v = s[j];
        bf16 hi = __float2bfloat16(v);
        h[j] = hi;
        l[j] = __float2bfloat16(v - __bfloat162float(hi));
    }
}

// ================= prep: Hm[t,p,e,r] -> HB[t][e][r*64+p] hi/lo =================
__global__ __launch_bounds__(256) void prep_hb_kernel(const float* __restrict__ Hm) {
    __shared__ float tile[64][65];              // [p][r]
    const int t = blockIdx.x >> 7;
    const int e = blockIdx.x & 127;
    const int tid = threadIdx.x;
    for (int i = tid; i < 64 * 64; i += 256) {
        int p = i >> 6, r = i & 63;
        tile[p][r] = Hm[(((size_t)(t * 64 + p) * 128) + e) * 64 + r];
    }
    __syncthreads();
    bf16* dh = g_HBh + (size_t)(t * 128 + e) * 4096;
    bf16* dl = g_HBl + (size_t)(t * 128 + e) * 4096;
    for (int c = tid; c < 4096; c += 256) {
        int r = c >> 6, p = c & 63;
        float v = tile[p][r];
        bf16 hi = __float2bfloat16(v);
        dh[c] = hi;
        dl[c] = __float2bfloat16(v - __bfloat162float(hi));
    }
}

// ================= encoder v2: 256 threads, 64 rows/CTA =================
// smem: xs_hi/lo 64x72, hs_hi/lo 64x520, stg 8x(16x20)f32
#define EX_H 0u
#define EX_L (EX_H + 64u * 72u * 2u)
#define EH_H (EX_L + 64u * 72u * 2u)
#define EH_L (EH_H + 64u * 520u * 2u)
#define E_ST (EH_L + 64u * 520u * 2u)
#define ENC2_SMEM (E_ST + 8u * 320u * 4u)     // 161792 B

__global__ __launch_bounds__(256, 1) void encoder2_kernel(const float* __restrict__ x,
                                                          const float* __restrict__ b1,
                                                          const float* __restrict__ b2) {
    extern __shared__ char smem[];
    bf16* xs_hi = (bf16*)(smem + EX_H);
    bf16* xs_lo = (bf16*)(smem + EX_L);
    bf16* hs_hi = (bf16*)(smem + EH_H);
    bf16* hs_lo = (bf16*)(smem + EH_L);
    float* stg_base = (float*)(smem + E_ST);

    const int tid = threadIdx.x, w = tid >> 5, lane = tid & 31;
    const int wy = w >> 2, wx = w & 3;
    const int n0 = blockIdx.x * 64;
    float* stg = stg_base + w * 320;
    const int frow = lane >> 1, fcol = (lane & 1) * 8;

    // load + split x tile [64 x 64]
    #pragma unroll
    for (int k = 0; k < 16; k++) {
        int idx = tid + k * 256;
        int r = idx >> 6, c = idx & 63;
        float v = x[(size_t)(n0 + r) * DIN + c];
        bf16 hi = __float2bfloat16(v);
        xs_hi[r * 72 + c] = hi;
        xs_lo[r * 72 + c] = __float2bfloat16(v - __bfloat162float(hi));
    }
    __syncthreads();

    // ---- stage 1: h[64,512] = relu(x @ W1^T + b1), warp = 32 rows x 128 cols (2 passes of 64) ----
    #pragma unroll
    for (int pass = 0; pass < 2; pass++) {
        const int cb = wx * 128 + pass * 64;
        wmma::fragment<wmma::accumulator, 16, 16, 16, float> acc[2][4];
        #pragma unroll
        for (int rf = 0; rf < 2; rf++)
            #pragma unroll
            for (int j = 0; j < 4; j++) wmma::fill_fragment(acc[rf][j], 0.0f);
        #pragma unroll
        for (int kk = 0; kk < 4; kk++) {
            wmma::fragment<wmma::matrix_a, 16, 16, 16, bf16, wmma::row_major> ahi[2], alo[2];
            #pragma unroll
            for (int rf = 0; rf < 2; rf++) {
                wmma::load_matrix_sync(ahi[rf], xs_hi + (wy * 32 + rf * 16) * 72 + kk * 16, 72);
                wmma::load_matrix_sync(alo[rf], xs_lo + (wy * 32 + rf * 16) * 72 + kk * 16, 72);
            }
            #pragma unroll
            for (int j = 0; j < 4; j++) {
                wmma::fragment<wmma::matrix_b, 16, 16, 16, bf16, wmma::col_major> bhi, blo;
                wmma::load_matrix_sync(bhi, g_W1hi + (cb + j * 16) * DIN + kk * 16, DIN);
                wmma::load_matrix_sync(blo, g_W1lo + (cb + j * 16) * DIN + kk * 16, DIN);
                #pragma unroll
                for (int rf = 0; rf < 2; rf++) {
                    wmma::mma_sync(acc[rf][j], ahi[rf], bhi, acc[rf][j]);
                    wmma::mma_sync(acc[rf][j], alo[rf], bhi, acc[rf][j]);
                    wmma::mma_sync(acc[rf][j], ahi[rf], blo, acc[rf][j]);
                }
            }
        }
        // epilogue: per fragment, 8 els/lane
        #pragma unroll
        for (int rf = 0; rf < 2; rf++)
            #pragma unroll
            for (int j = 0; j < 4; j++) {
                wmma::store_matrix_sync(stg, acc[rf][j], 20, wmma::mem_row_major);
                __syncwarp();
                const int rbase = wy * 32 + rf * 16 + frow;
                #pragma unroll
                for (int cc = 0; cc < 8; cc++) {
                    int gc = cb + j * 16 + fcol + cc;
                    float v = fmaxf(stg[frow * 20 + fcol + cc] + b1[gc], 0.0f);
                    bf16 hi = __float2bfloat16(v);
                    hs_hi[rbase * 520 + gc] = hi;
                    hs_lo[rbase * 520 + gc] = __float2bfloat16(v - __bfloat162float(hi));
                }
                __syncwarp();
            }
    }
    __syncthreads();

    // ---- stage 2: enc[64,128] = relu(h @ W2^T + b2), warp = 32 rows x 32 cols ----
    {
        wmma::fragment<wmma::accumulator, 16, 16, 16, float> acc[2][2];
        #pragma unroll
        for (int rf = 0; rf < 2; rf++)
            #pragma unroll
            for (int j = 0; j < 2; j++) wmma::fill_fragment(acc[rf][j], 0.0f);
        #pragma unroll 8
        for (int kk = 0; kk < 32; kk++) {
            wmma::fragment<wmma::matrix_a, 16, 16, 16, bf16, wmma::row_major> ahi[2], alo[2];
            #pragma unroll
            for (int rf = 0; rf < 2; rf++) {
                wmma::load_matrix_sync(ahi[rf], hs_hi + (wy * 32 + rf * 16) * 520 + kk * 16, 520);
                wmma::load_matrix_sync(alo[rf], hs_lo + (wy * 32 + rf * 16) * 520 + kk * 16, 520);
            }
            #pragma unroll
            for (int j = 0; j < 2; j++) {
                wmma::fragment<wmma::matrix_b, 16, 16, 16, bf16, wmma::col_major> bhi, blo;
                wmma::load_matrix_sync(bhi, g_W2hi + (wx * 32 + j * 16) * HID + kk * 16, HID);
                wmma::load_matrix_sync(blo, g_W2lo + (wx * 32 + j * 16) * HID + kk * 16, HID);
                #pragma unroll
                for (int rf = 0; rf < 2; rf++) {
                    wmma::mma_sync(acc[rf][j], ahi[rf], bhi, acc[rf][j]);
                    wmma::mma_sync(acc[rf][j], alo[rf], bhi, acc[rf][j]);
                    wmma::mma_sync(acc[rf][j], ahi[rf], blo, acc[rf][j]);
                }
            }
        }
        #pragma unroll
        for (int rf = 0; rf < 2; rf++)
            #pragma unroll
            for (int j = 0; j < 2; j++) {
                wmma::store_matrix_sync(stg, acc[rf][j], 20, wmma::mem_row_major);
                __syncwarp();
                const int n = n0 + wy * 32 + rf * 16 + frow;
                const int b = n / Tn, tt = n % Tn;
                #pragma unroll
                for (int cc = 0; cc < 8; cc++) {
                    int e = wx * 32 + j * 16 + fcol + cc;
                    float v = fmaxf(stg[frow * 20 + fcol + cc] + b2[e], 0.0f);
                    bf16 hi = __float2bfloat16(v);
                    g_ench[(size_t)(tt * Bsz + b) * ENCD + e] = hi;
                    g_encl[(size_t)(tt * Bsz + b) * ENCD + e] = __float2bfloat16(v - __bfloat162float(hi));
                }
                __syncwarp();
            }
    }
}

// ================= v0 = enc[:,0] @ H_first =================
__global__ __launch_bounds__(256) void v0_kernel(const float* __restrict__ Hf) {
    __shared__ float hf_s[ENCD * Rr];
    __shared__ float enc_s[16][ENCD];
    const int tid = threadIdx.x;
    const int b0 = blockIdx.x * 16;
    for (int i = tid; i < ENCD * Rr; i += 256) hf_s[i] = Hf[i];
    for (int i = tid; i < 16 * ENCD; i += 256) {
        int j = i >> 7, e = i & 127;
        size_t a = (size_t)(b0 + j) * ENCD + e;
        enc_s[j][e] = __bfloat162float(g_ench[a]) + __bfloat162float(g_encl[a]);
    }
    __syncthreads();
    const int r = tid & 63, g = tid >> 6;
    for (int pass = 0; pass < 4; pass++) {
        int j = g * 4 + pass;
        float acc = 0.0f;
        for (int e = 0; e < ENCD; e++) acc += enc_s[j][e] * hf_s[e * 64 + r];
        g_v[0][(b0 + j) * 64 + r] = acc;
    }
}

// ================= chain v3: single-wave streaming, A+v resident =================
// grid 128 CTAs x 256 threads. CTA: 64 batch rows, all 4096 cols in 16 n-blocks.
// B streamed in 64 chunks (32k x 256n), 2-stage cp.async. Warp = 32 rows x 64 cols (one r).
#define CAP 136      // A row pad (bf16)
#define CBP 264      // B row pad (bf16)
#define C_AH 0u
#define C_AL (C_AH + 64u * CAP * 2u)               // 17408
#define C_V  (C_AL + 64u * CAP * 2u)               // 34816
#define C_BH (C_V + 64u * 65u * 4u)                // 51456
#define C_BL (C_BH + 2u * 32u * CBP * 2u)          // 85248
#define C_ST (C_BL + 2u * 32u * CBP * 2u)          // 119040
#define CH3_SMEM (C_ST + 8u * 320u * 4u)           // 129280 B
#define B_STAGE_B (32u * CBP * 2u)                 // 16896 B per stage

__global__ __launch_bounds__(256, 1) void chain_stream_kernel(int t) {
    extern __shared__ char smem[];
    bf16* As_h = (bf16*)(smem + C_AH);
    bf16* As_l = (bf16*)(smem + C_AL);
    float* v_s = (float*)(smem + C_V);
    float* stg_base = (float*)(smem + C_ST);

    const int tid = threadIdx.x, wid = tid >> 5, lane = tid & 31;
    const int wy = wid >> 2, wx = wid & 3;
    const int b0 = blockIdx.x * 64;

    const bf16* Eh  = g_ench + (size_t)(t + 1) * Bsz * ENCD;
    const bf16* El  = g_encl + (size_t)(t + 1) * Bsz * ENCD;
    const bf16* HBh = g_HBh + (size_t)t * ENCD * 4096;
    const bf16* HBl = g_HBl + (size_t)t * ENCD * 4096;
    const float* vin  = g_v[t & 1];
    float*       vout = g_v[(t & 1) ^ 1];

    // async-load B chunk g (= nb*4 + c) into stage s
    auto load_B = [&](int g, int s) {
        const int nb = g >> 2, c = g & 3;
        const int k0 = c * 32, cb = nb * 256;
        bf16* Bh = (bf16*)(smem + C_BH + s * B_STAGE_B);
        bf16* Bl = (bf16*)(smem + C_BL + s * B_STAGE_B);
        #pragma unroll
        for (int q = 0; q < 4; q++) {
            int idx = tid + q * 256;
            int e = idx >> 5, cq = (idx & 31) * 8;
            cp16(smem_u32(Bh + e * CBP + cq), HBh + (size_t)(k0 + e) * 4096 + cb + cq);
            cp16(smem_u32(Bl + e * CBP + cq), HBl + (size_t)(k0 + e) * 4096 + cb + cq);
        }
        CP_COMMIT();
    };

    load_B(0, 0);

    // A resident: 64 rows x 128 k (hi/lo)
    #pragma unroll
    for (int k = 0; k < 4; k++) {
        int i = tid + k * 256;
        int r = i >> 4, sl = (i & 15) * 8;
        *(uint4*)(As_h + r * CAP + sl) = *(const uint4*)(Eh + (size_t)(b0 + r) * ENCD + sl);
        *(uint4*)(As_l + r * CAP + sl) = *(const uint4*)(El + (size_t)(b0 + r) * ENCD + sl);
    }
    // v resident
    #pragma unroll
    for (int q = 0; q < 16; q++) {
        int i = tid + q * 256;
        int m = i >> 6, p = i & 63;
        v_s[m * 65 + p] = vin[(size_t)(b0 + m) * 64 + p];
    }

    float* stg = stg_base + wid * 320;
    const int frow = lane >> 1, half = lane & 1;

    wmma::fragment<wmma::accumulator, 16, 16, 16, float> acc[2][4];
    #pragma unroll
    for (int rf = 0; rf < 2; rf++)
        #pragma unroll
        for (int j = 0; j < 4; j++) wmma::fill_fragment(acc[rf][j], 0.0f);

    for (int g = 0; g < 64; g++) {
        const int s = g & 1;
        if (g < 63) { load_B(g + 1, s ^ 1); CP_WAIT(1); }
        else        { CP_WAIT(0); }
        __syncthreads();

        const int c = g & 3;            // k-chunk within K=128
        const int k0 = c * 32;
        bf16* Bh = (bf16*)(smem + C_BH + s * B_STAGE_B);
        bf16* Bl = (bf16*)(smem + C_BL + s * B_STAGE_B);
        #pragma unroll
        for (int kk = 0; kk < 2; kk++) {
            wmma::fragment<wmma::matrix_a, 16, 16, 16, bf16, wmma::row_major> ahi[2], alo[2];
            #pragma unroll
            for (int rf = 0; rf < 2; rf++) {
                wmma::load_matrix_sync(ahi[rf], As_h + (wy * 32 + rf * 16) * CAP + k0 + kk * 16, CAP);
                wmma::load_matrix_sync(alo[rf], As_l + (wy * 32 + rf * 16) * CAP + k0 + kk * 16, CAP);
            }
            #pragma unroll
            for (int j = 0; j < 4; j++) {
                wmma::fragment<wmma::matrix_b, 16, 16, 16, bf16, wmma::row_major> bhi, blo;
                wmma::load_matrix_sync(bhi, Bh + (kk * 16) * CBP + wx * 64 + j * 16, CBP);
                wmma::load_matrix_sync(blo, Bl + (kk * 16) * CBP + wx * 64 + j * 16, CBP);
                #pragma unroll
                for (int rf = 0; rf < 2; rf++) {
                    wmma::mma_sync(acc[rf][j], ahi[rf], bhi, acc[rf][j]);
                    wmma::mma_sync(acc[rf][j], alo[rf], bhi, acc[rf][j]);
                    wmma::mma_sync(acc[rf][j], ahi[rf], blo, acc[rf][j]);
                }
            }
        }

        if ((g & 3) == 3) {
            // epilogue for n-block nb = g>>2: reduce over p against v, write vout
            const int nb = g >> 2;
            const int r_glob = nb * 4 + wx;
            #pragma unroll
            for (int rf = 0; rf < 2; rf++) {
                float racc = 0.f;
                #pragma unroll
                for (int j = 0; j < 4; j++) {
                    wmma::store_matrix_sync(stg, acc[rf][j], 20, wmma::mem_row_major);
                    __syncwarp();
                    const int p0 = j * 16 + half * 8;
                    const int bl = wy * 32 + rf * 16 + frow;
                    float ssum = 0.f;
                    #pragma unroll
                    for (int cc = 0; cc < 8; cc++)
                        ssum += stg[frow * 20 + half * 8 + cc] * v_s[bl * 65 + p0 + cc];
                    ssum += __shfl_xor_sync(0xffffffffu, ssum, 1);
                    racc += ssum;
                    __syncwarp();
                    wmma::fill_fragment(acc[rf][j], 0.0f);
                }
                if (half == 0) {
                    int b = b0 + wy * 32 + rf * 16 + frow;
                    vout[(size_t)b * 64 + r_glob] = racc;
                }
            }
        }
        __syncthreads();
    }
}

// ================= final: out[b] = v . (H_last @ enc[:,T-1]) =================
__global__ __launch_bounds__(256) void final_kernel(const float* __restrict__ Hl,
                                                    float* __restrict__ out) {
    __shared__ float hl_t[ENCD * Rr];
    __shared__ float enc_s[16][ENCD];
    __shared__ float red2[16][2];
    const int tid = threadIdx.x;
    const int b0 = blockIdx.x * 16;
    for (int i = tid; i < ENCD * Rr; i += 256) {
        int e = i >> 6, p = i & 63;
        hl_t[i] = Hl[p * ENCD + e];
    }
    for (int i = tid; i < 16 * ENCD; i += 256) {
        int j = i >> 7, e = i & 127;
        size_t a = (size_t)((Tn - 1) * Bsz + b0 + j) * ENCD + e;
        enc_s[j][e] = __bfloat162float(g_ench[a]) + __bfloat162float(g_encl[a]);
    }
    __syncthreads();
    const int p = tid & 63, g = tid >> 6;
    const int warp = tid >> 5, half = warp & 1;
    for (int pass = 0; pass < 4; pass++) {
        int j = g * 4 + pass;
        float last = 0.0f;
        for (int e = 0; e < ENCD; e++) last += enc_s[j][e] * hl_t[e * 64 + p];
        float partial = g_v[0][(b0 + j) * 64 + p] * last;
        for (int off = 16; off > 0; off >>= 1)
            partial += __shfl_down_sync(0xffffffffu, partial, off);
        if ((tid & 31) == 0) red2[j][half] = partial;
    }
    __syncthreads();
    if (tid < 16) out[b0 + tid] = red2[tid][0] + red2[tid][1];
}

// ================= host launcher =================
extern "C" void kernel_launch(void* const* d_in, const int* in_sizes, int n_in,
                              void* d_out, int out_size) {
    const float* x  = (const float*)d_in[0];
    const float* W1 = (const float*)d_in[1];
    const float* b1 = (const float*)d_in[2];
    const float* W2 = (const float*)d_in[3];
    const float* b2 = (const float*)d_in[4];
    const float* Hf = (const float*)d_in[5];
    const float* Hm = (const float*)d_in[6];
    const float* Hl = (const float*)d_in[7];
    float* out = (float*)d_out;

    cudaFuncSetAttribute(encoder2_kernel,     cudaFuncAttributeMaxDynamicSharedMemorySize, ENC2_SMEM);
    cudaFuncSetAttribute(chain_stream_kernel, cudaFuncAttributeMaxDynamicSharedMemorySize, CH3_SMEM);

    prep_w_kernel<<<96, 256>>>(W1, W2);
    prep_hb_kernel<<<(Tn - 2) * ENCD, 256>>>(Hm);
    encoder2_kernel<<<(Bsz * Tn) / 64, 256, ENC2_SMEM>>>(x, b1, b2);
    v0_kernel<<<Bsz / 16, 256>>>(Hf);
    for (int t = 0; t < Tn - 2; t++)
        chain_stream_kernel<<<128, 256, CH3_SMEM>>>(t);
    final_kernel<<<Bsz / 16, 256>>>(Hl, out);
}